// round 10
// baseline (speedup 1.0000x reference)
#include <cuda_runtime.h>
#include <math.h>

#define H 512
#define W 512
#define HW (512*512)
#define NB 8          // batch
#define NIMG 16       // 8 pred + 8 true
#define NUM_ITER 40
#define NFUSED (NUM_ITER/2)   // 20 fused double-steps
#define BH 16
#define NBANDS (H/BH)   // 32
#define BIGF 3.0e38f

// ---- scratch (device globals; no allocation) ----
// g_skel stores q = 1 - skel  (multiplicative form: q *= (1 - delta))
__device__ float g_imgA[(size_t)NIMG*HW];
__device__ float g_imgB[(size_t)NIMG*HW];
__device__ float g_skel[(size_t)NIMG*HW];
__device__ float g_dicePart[256*3];           // [block][inter,sumT,sumP]
__device__ float g_epPart[NIMG*NBANDS*3];     // [img][band][s,sy,sx]

__device__ __forceinline__ float f3min(float a,float b,float c){return fminf(fminf(a,b),c);}
__device__ __forceinline__ float f3max(float a,float b,float c){return fmaxf(fmaxf(a,b),c);}

// ---------------------------------------------------------------------------
// prep: prob = softmax(net)[:,1] = sigmoid(x1-x0); true->float; dice partials.
// ---------------------------------------------------------------------------
__global__ void prep_kernel(const float* __restrict__ net, const int* __restrict__ yt) {
    int tid = blockIdx.x * 256 + threadIdx.x;
    float inter = 0.f, st = 0.f, sp = 0.f;
    for (int idx = tid; idx < NB*HW; idx += 256*256) {
        int b = idx / HW;
        int p = idx - b*HW;
        float x0 = net[(size_t)b*2*HW + p];
        float x1 = net[(size_t)b*2*HW + HW + p];
        float prob = 1.f / (1.f + __expf(x0 - x1));
        float t = (float)yt[idx];
        g_imgA[(size_t)b*HW + p] = prob;
        g_imgA[(size_t)(NB + b)*HW + p] = t;
        inter += t * prob;
        st += t;
        sp += prob;
    }
    __shared__ float s[3][256];
    s[0][threadIdx.x] = inter; s[1][threadIdx.x] = st; s[2][threadIdx.x] = sp;
    __syncthreads();
    for (int off = 128; off > 0; off >>= 1) {
        if (threadIdx.x < off) {
            s[0][threadIdx.x] += s[0][threadIdx.x + off];
            s[1][threadIdx.x] += s[1][threadIdx.x + off];
            s[2][threadIdx.x] += s[2][threadIdx.x + off];
        }
        __syncthreads();
    }
    if (threadIdx.x == 0) {
        g_dicePart[blockIdx.x*3 + 0] = s[0][0];
        g_dicePart[blockIdx.x*3 + 1] = s[1][0];
        g_dicePart[blockIdx.x*3 + 2] = s[2][0];
    }
}

// ---------------------------------------------------------------------------
// INIT sweep: q = 1 - relu(img - dilate3x3(erode(img))).  (single launch)
// ---------------------------------------------------------------------------
__global__ __launch_bounds__(128) void sweep_init_kernel() {
    const int img = blockIdx.y;
    const int R0row = blockIdx.x * BH;
    const int lane = threadIdx.x & 31;
    const int colBase = ((threadIdx.x >> 5) << 7) + (lane << 2);
    const bool isL = (lane == 0), isR = (lane == 31);
    const bool edgeL = (colBase == 0), edgeR = (colBase == W-4);
    const float* __restrict__ in = g_imgA + (size_t)img*HW;
    float* __restrict__ skel = g_skel + (size_t)img*HW;

    const float4 PINF = make_float4(BIGF,BIGF,BIGF,BIGF);
    float4 i0=PINF, i1=PINF, L0=PINF, L1=PINF, Rv0=PINF, Rv1=PINF;
    float4 hp=PINF; float hpL1=BIGF, hpR0=BIGF;
    float4 e1a=make_float4(-BIGF,-BIGF,-BIGF,-BIGF), e1b=e1a;
    float e1aL=-BIGF, e1bL=-BIGF, e1aR=-BIGF, e1bR=-BIGF;

    const int rStart = R0row-2, rEnd = R0row+BH+1;   // BH+4 = 20 rows
    float4 nCur=PINF, nL=PINF, nR=PINF;
    if (rStart >= 0 && rStart < H) {
        const float* p = in + rStart*W + colBase;
        nCur = *(const float4*)p;
        if (isL && !edgeL) nL = *(const float4*)(p - 4);
        if (isR && !edgeR) nR = *(const float4*)(p + 4);
    }

    #pragma unroll 2
    for (int t = 0; t < BH+4; t++) {
        const int r = rStart + t;
        float4 cur = nCur, Lc = nL, Rc = nR;
        nCur = PINF; nL = PINF; nR = PINF;
        {
            int rn = r + 1;
            if (rn <= rEnd && (unsigned)rn < (unsigned)H) {
                const float* p = in + rn*W + colBase;
                nCur = *(const float4*)p;
                if (isL && !edgeL) nL = *(const float4*)(p - 4);
                if (isR && !edgeR) nR = *(const float4*)(p + 4);
            }
        }
        float xm1 = __shfl_up_sync(0xffffffffu, cur.w, 1); if (isL) xm1 = Lc.w;
        float xp1 = __shfl_down_sync(0xffffffffu, cur.x, 1); if (isR) xp1 = Rc.x;
        float4 hc;
        hc.x = f3min(xm1, cur.x, cur.y);
        hc.y = f3min(cur.x, cur.y, cur.z);
        hc.z = f3min(cur.y, cur.z, cur.w);
        hc.w = f3min(cur.z, cur.w, xp1);
        float hcL1 = f3min(Lc.z, Lc.w, cur.x);
        float hcR0 = f3min(cur.w, Rc.x, Rc.y);

        float4 e1n;
        e1n.x = fminf(f3min(i0.x,i1.x,cur.x), hp.x);
        e1n.y = fminf(f3min(i0.y,i1.y,cur.y), hp.y);
        e1n.z = fminf(f3min(i0.z,i1.z,cur.z), hp.z);
        e1n.w = fminf(f3min(i0.w,i1.w,cur.w), hp.w);
        float e1nL = fminf(f3min(L0.w,L1.w,Lc.w), hpL1);
        float e1nR = fminf(f3min(Rv0.x,Rv1.x,Rc.x), hpR0);
        {
            int k = r-1;
            if (k < 0 || k >= H) {
                e1n = make_float4(-BIGF,-BIGF,-BIGF,-BIGF);
                e1nL = e1nR = -BIGF;
            }
        }
        if (edgeL) e1nL = -BIGF;
        if (edgeR) e1nR = -BIGF;

        if (t >= 4) {   // r >= R0row+2
            float4 mv;
            mv.x = f3max(e1a.x, e1b.x, e1n.x);
            mv.y = f3max(e1a.y, e1b.y, e1n.y);
            mv.z = f3max(e1a.z, e1b.z, e1n.z);
            mv.w = f3max(e1a.w, e1b.w, e1n.w);
            float mvL = f3max(e1aL, e1bL, e1nL);
            float mvR = f3max(e1aR, e1bR, e1nR);
            float mm1 = __shfl_up_sync(0xffffffffu, mv.w, 1); if (isL) mm1 = mvL;
            float mp1 = __shfl_down_sync(0xffffffffu, mv.x, 1); if (isR) mp1 = mvR;
            float4 open;
            open.x = f3max(mm1, mv.x, mv.y);
            open.y = f3max(mv.x, mv.y, mv.z);
            open.z = f3max(mv.y, mv.z, mv.w);
            open.w = f3max(mv.z, mv.w, mp1);
            int k2 = r-2;
            float4 s;
            s.x = 1.f - fmaxf(i0.x - open.x, 0.f);
            s.y = 1.f - fmaxf(i0.y - open.y, 0.f);
            s.z = 1.f - fmaxf(i0.z - open.z, 0.f);
            s.w = 1.f - fmaxf(i0.w - open.w, 0.f);
            *(float4*)(skel + k2*W + colBase) = s;
        }
        i0=i1; i1=cur; L0=L1; L1=Lc; Rv0=Rv1; Rv1=Rc;
        hp=hc; hpL1=hcL1; hpR0=hcR0;
        e1a=e1b; e1b=e1n; e1aL=e1bL; e1bL=e1nL; e1aR=e1bR; e1bR=e1nR;
    }
}

// ---------------------------------------------------------------------------
// FUSED double-step body. Computes TWO soft-skel iterations per launch.
// Streams: img -> E1 -> E2 -> E3 (E2 = erode(E1) serves iter1's open AND
// iter2's first erode; output image = E2).
//   delta1 = relu(E1 - dilate3(E2));  delta2 = relu(E2 - dilate3(E3))
//   q *= (1-delta1)*(1-delta2)
// Pipeline: load img[r] -> E1[r-1] -> E2[r-2] -> E3[r-3] -> out[r-4].
// Rows t=0..BH+7 (24). Sentinels: erode-input OOB -> +INF; dilate-input -> -INF.
// E2 stored e-flavor (+INF at OOB rows), flipped to -INF at rotation once its
// erode-uses are done (slots: fresh/b/a are e-uses; live d-uses happen later).
// ---------------------------------------------------------------------------
template<bool BOUNDARY>
__device__ __forceinline__ void step2_body(
    const float* __restrict__ in, float* __restrict__ outImg,
    float* __restrict__ skel, int R0row, int colBase,
    bool isL, bool isR, bool edgeL, bool edgeR)
{
    const float4 PINF = make_float4(BIGF,BIGF,BIGF,BIGF);
    const float4 NINF = make_float4(-BIGF,-BIGF,-BIGF,-BIGF);

    float4 i0=PINF, i1=PINF, L0=PINF, L1=PINF, Rv0=PINF, Rv1=PINF;
    float4 hp=PINF; float hpL3=BIGF,hpL2=BIGF,hpL1=BIGF,hpR0=BIGF,hpR1=BIGF,hpR2=BIGF;
    float4 e1b=PINF, e1a=PINF, e1z=PINF;
    float e1bL2=BIGF,e1bL1=BIGF,e1bR0=BIGF,e1bR1=BIGF;
    float e1aL2=BIGF,e1aL1=BIGF,e1aR0=BIGF,e1aR1=BIGF;
    float4 h1p=PINF; float h1pL2=BIGF,h1pL1=BIGF,h1pR0=BIGF,h1pR1=BIGF;
    float4 e2b=PINF, e2a=PINF, e2c=PINF;
    float e2bL1=BIGF,e2bR0=BIGF,e2aL1=BIGF,e2aR0=BIGF,e2cL1=BIGF,e2cR0=BIGF;
    float4 h2p=PINF; float h2pL1=BIGF,h2pR0=BIGF;
    float4 e3b=NINF, e3a=NINF;
    float e3bL1=-BIGF,e3bR0=-BIGF,e3aL1=-BIGF,e3aR0=-BIGF;

    const int rStart = R0row-4;   // rows r = rStart .. rStart+BH+7
    // 1-row img prefetch
    float4 pC=PINF, pL=PINF, pR=PINF;
    if (!BOUNDARY || ((unsigned)rStart < (unsigned)H)) {
        const float* p = in + rStart*W + colBase;
        pC = *(const float4*)p;
        if (isL && !edgeL) pL = *(const float4*)(p - 4);
        if (isR && !edgeR) pR = *(const float4*)(p + 4);
    }

    #pragma unroll 2
    for (int t = 0; t < BH+8; t++) {
        const int r = rStart + t;
        float4 cur = pC, Lc = pL, Rc = pR;
        // prefetch row r+1
        {
            int rn = r + 1;
            if (BOUNDARY) {
                pC = PINF; pL = PINF; pR = PINF;
                if ((unsigned)rn < (unsigned)H && rn <= rStart+BH+8) {
                    const float* p = in + rn*W + colBase;
                    pC = *(const float4*)p;
                    if (isL && !edgeL) pL = *(const float4*)(p - 4);
                    if (isR && !edgeR) pR = *(const float4*)(p + 4);
                }
            } else {
                const float* p = in + rn*W + colBase;
                pC = *(const float4*)p;
                pL = PINF; pR = PINF;
                if (isL && !edgeL) pL = *(const float4*)(p - 4);
                if (isR && !edgeR) pR = *(const float4*)(p + 4);
            }
        }

        // --- stage A: hc = hmin3(img[r]), cols -3..+6 ---
        float xm1 = __shfl_up_sync(0xffffffffu, cur.w, 1); if (isL) xm1 = Lc.w;
        float xp1 = __shfl_down_sync(0xffffffffu, cur.x, 1); if (isR) xp1 = Rc.x;
        float4 hc;
        hc.x = f3min(xm1, cur.x, cur.y);
        hc.y = f3min(cur.x, cur.y, cur.z);
        hc.z = f3min(cur.y, cur.z, cur.w);
        hc.w = f3min(cur.z, cur.w, xp1);
        float hcL3 = f3min(Lc.x, Lc.y, Lc.z);
        float hcL2 = f3min(Lc.y, Lc.z, Lc.w);
        float hcL1 = f3min(Lc.z, Lc.w, cur.x);
        float hcR0 = f3min(cur.w, Rc.x, Rc.y);
        float hcR1 = f3min(Rc.x, Rc.y, Rc.z);
        float hcR2 = f3min(Rc.y, Rc.z, Rc.w);

        // --- stage B: E1[r-1] = min(vmin3(img), hmin3(img)), cols -3..+6 ---
        float4 e1n;
        e1n.x = fminf(f3min(i0.x,i1.x,cur.x), hp.x);
        e1n.y = fminf(f3min(i0.y,i1.y,cur.y), hp.y);
        e1n.z = fminf(f3min(i0.z,i1.z,cur.z), hp.z);
        e1n.w = fminf(f3min(i0.w,i1.w,cur.w), hp.w);
        float e1nL3 = fminf(f3min(L0.y,L1.y,Lc.y), hpL3);
        float e1nL2 = fminf(f3min(L0.z,L1.z,Lc.z), hpL2);
        float e1nL1 = fminf(f3min(L0.w,L1.w,Lc.w), hpL1);
        float e1nR0 = fminf(f3min(Rv0.x,Rv1.x,Rc.x), hpR0);
        float e1nR1 = fminf(f3min(Rv0.y,Rv1.y,Rc.y), hpR1);
        float e1nR2 = fminf(f3min(Rv0.z,Rv1.z,Rc.z), hpR2);
        if (BOUNDARY) {
            int k = r-1;
            if (k < 0 || k >= H) {
                e1n = PINF;
                e1nL3=e1nL2=e1nL1=e1nR0=e1nR1=e1nR2=BIGF;
            }
        }

        // --- stage C: h1c = hmin3(E1[r-1]), cols -2..+5 ---
        float em1 = __shfl_up_sync(0xffffffffu, e1n.w, 1); if (isL) em1 = e1nL1;
        float ep1 = __shfl_down_sync(0xffffffffu, e1n.x, 1); if (isR) ep1 = e1nR0;
        float4 h1c;
        h1c.x = f3min(em1, e1n.x, e1n.y);
        h1c.y = f3min(e1n.x, e1n.y, e1n.z);
        h1c.z = f3min(e1n.y, e1n.z, e1n.w);
        h1c.w = f3min(e1n.z, e1n.w, ep1);
        float h1cL2 = f3min(e1nL3, e1nL2, e1nL1);
        float h1cL1 = f3min(e1nL2, e1nL1, e1n.x);
        float h1cR0 = f3min(e1n.w, e1nR0, e1nR1);
        float h1cR1 = f3min(e1nR0, e1nR1, e1nR2);

        // --- stage D: E2[r-2] = min(vmin3(E1), h1p), cols -2..+5 (e-flavor) ---
        float4 e2n;
        e2n.x = fminf(f3min(e1a.x,e1b.x,e1n.x), h1p.x);
        e2n.y = fminf(f3min(e1a.y,e1b.y,e1n.y), h1p.y);
        e2n.z = fminf(f3min(e1a.z,e1b.z,e1n.z), h1p.z);
        e2n.w = fminf(f3min(e1a.w,e1b.w,e1n.w), h1p.w);
        float e2nL2 = fminf(f3min(e1aL2,e1bL2,e1nL2), h1pL2);
        float e2nL1 = fminf(f3min(e1aL1,e1bL1,e1nL1), h1pL1);
        float e2nR0 = fminf(f3min(e1aR0,e1bR0,e1nR0), h1pR0);
        float e2nR1 = fminf(f3min(e1aR1,e1bR1,e1nR1), h1pR1);
        if (BOUNDARY) {
            int j = r-2;
            if (j < 0 || j >= H) {
                e2n = PINF;
                e2nL2=e2nL1=e2nR0=e2nR1=BIGF;
            }
        }

        // --- stage E: h2c = hmin3(E2[r-2]), cols -1..+4 ---
        float em2 = __shfl_up_sync(0xffffffffu, e2n.w, 1); if (isL) em2 = e2nL1;
        float ep2 = __shfl_down_sync(0xffffffffu, e2n.x, 1); if (isR) ep2 = e2nR0;
        float4 h2c;
        h2c.x = f3min(em2, e2n.x, e2n.y);
        h2c.y = f3min(e2n.x, e2n.y, e2n.z);
        h2c.z = f3min(e2n.y, e2n.z, e2n.w);
        h2c.w = f3min(e2n.z, e2n.w, ep2);
        float h2cL1 = f3min(e2nL2, e2nL1, e2n.x);
        float h2cR0 = f3min(e2n.w, e2nR0, e2nR1);

        // --- stage F: E3[r-3] = min(vmin3(E2), h2p), cols -1..+4 (dilate input) ---
        float4 e3n;
        e3n.x = fminf(f3min(e2a.x,e2b.x,e2n.x), h2p.x);
        e3n.y = fminf(f3min(e2a.y,e2b.y,e2n.y), h2p.y);
        e3n.z = fminf(f3min(e2a.z,e2b.z,e2n.z), h2p.z);
        e3n.w = fminf(f3min(e2a.w,e2b.w,e2n.w), h2p.w);
        float e3nL1 = edgeL ? -BIGF : fminf(f3min(e2aL1,e2bL1,e2nL1), h2pL1);
        float e3nR0 = edgeR ? -BIGF : fminf(f3min(e2aR0,e2bR0,e2nR0), h2pR0);
        if (BOUNDARY) {
            int m = r-3;
            if (m < 0 || m >= H) {
                e3n = NINF;
                e3nL1 = e3nR0 = -BIGF;
            }
        }

        // --- stage G: output row r-4 ---
        if (t >= 8) {
            const int k2 = r-4;
            float4 q = *(const float4*)(skel + k2*W + colBase);
            // open1 = dilate3(E2) at row r-4 (rows r-5,r-4,r-3 = e2c,e2a,e2b)
            float4 vm;
            vm.x = f3max(e2c.x, e2a.x, e2b.x);
            vm.y = f3max(e2c.y, e2a.y, e2b.y);
            vm.z = f3max(e2c.z, e2a.z, e2b.z);
            vm.w = f3max(e2c.w, e2a.w, e2b.w);
            float vmL = edgeL ? -BIGF : f3max(e2cL1, e2aL1, e2bL1);
            float vmR = edgeR ? -BIGF : f3max(e2cR0, e2aR0, e2bR0);
            float mm1 = __shfl_up_sync(0xffffffffu, vm.w, 1); if (isL) mm1 = vmL;
            float mp1 = __shfl_down_sync(0xffffffffu, vm.x, 1); if (isR) mp1 = vmR;
            float4 o1;
            o1.x = f3max(mm1, vm.x, vm.y);
            o1.y = f3max(vm.x, vm.y, vm.z);
            o1.z = f3max(vm.y, vm.z, vm.w);
            o1.w = f3max(vm.z, vm.w, mp1);
            // open2 = dilate3(E3) at row r-4 (rows r-5,r-4,r-3 = e3a,e3b,e3n)
            float4 wm;
            wm.x = f3max(e3a.x, e3b.x, e3n.x);
            wm.y = f3max(e3a.y, e3b.y, e3n.y);
            wm.z = f3max(e3a.z, e3b.z, e3n.z);
            wm.w = f3max(e3a.w, e3b.w, e3n.w);
            float wmL = f3max(e3aL1, e3bL1, e3nL1);   // edge already -INF
            float wmR = f3max(e3aR0, e3bR0, e3nR0);
            float mm2 = __shfl_up_sync(0xffffffffu, wm.w, 1); if (isL) mm2 = wmL;
            float mp2 = __shfl_down_sync(0xffffffffu, wm.x, 1); if (isR) mp2 = wmR;
            float4 o2;
            o2.x = f3max(mm2, wm.x, wm.y);
            o2.y = f3max(wm.x, wm.y, wm.z);
            o2.z = f3max(wm.y, wm.z, wm.w);
            o2.w = f3max(wm.z, wm.w, mp2);
            // q *= (1-d1)*(1-d2);  d1 = relu(E1[r-4]-o1), d2 = relu(E2[r-4]-o2)
            float d;
            d = fmaxf(e1z.x - o1.x, 0.f); q.x -= q.x*d;
            d = fmaxf(e1z.y - o1.y, 0.f); q.y -= q.y*d;
            d = fmaxf(e1z.z - o1.z, 0.f); q.z -= q.z*d;
            d = fmaxf(e1z.w - o1.w, 0.f); q.w -= q.w*d;
            d = fmaxf(e2a.x - o2.x, 0.f); q.x -= q.x*d;
            d = fmaxf(e2a.y - o2.y, 0.f); q.y -= q.y*d;
            d = fmaxf(e2a.z - o2.z, 0.f); q.z -= q.z*d;
            d = fmaxf(e2a.w - o2.w, 0.f); q.w -= q.w*d;
            *(float4*)(skel + k2*W + colBase) = q;
            *(float4*)(outImg + k2*W + colBase) = e2a;   // new image = E2
        }

        // --- rotation ---
        i0=i1; i1=cur; L0=L1; L1=Lc; Rv0=Rv1; Rv1=Rc;
        hp=hc; hpL3=hcL3; hpL2=hcL2; hpL1=hcL1; hpR0=hcR0; hpR1=hcR1; hpR2=hcR2;
        e1z=e1a;
        e1a=e1b; e1aL2=e1bL2; e1aL1=e1bL1; e1aR0=e1bR0; e1aR1=e1bR1;
        e1b=e1n; e1bL2=e1nL2; e1bL1=e1nL1; e1bR0=e1nR0; e1bR1=e1nR1;
        h1p=h1c; h1pL2=h1cL2; h1pL1=h1cL1; h1pR0=h1cR0; h1pR1=h1cR1;
        e2c=e2a; e2cL1=e2aL1; e2cR0=e2aR0;
        e2a=e2b; e2aL1=e2bL1; e2aR0=e2bR0;
        e2b=e2n; e2bL1=e2nL1; e2bR0=e2nR0;
        h2p=h2c; h2pL1=h2cL1; h2pR0=h2cR0;
        e3a=e3b; e3aL1=e3bL1; e3aR0=e3bR0;
        e3b=e3n; e3bL1=e3nL1; e3bR0=e3nR0;
        if (BOUNDARY) {
            // flip E2 rows to dilate-flavor once erode-uses are done.
            // (next step r'=r+1: e2b holds row r-2, e2c holds row r-4)
            if (r-2 >= H) { e2b = NINF; e2bL1 = e2bR0 = -BIGF; }   // bottom
            if (r-4 < 0 || r-4 >= H) { e2c = NINF; e2cL1 = e2cR0 = -BIGF; }
        }
    }
}

__global__ __launch_bounds__(128, 4) void sweep_step2_kernel(int bufsel) {
    const int img = blockIdx.y;
    const int band = blockIdx.x;
    const int R0row = band * BH;
    const int lane = threadIdx.x & 31;
    const int colBase = ((threadIdx.x >> 5) << 7) + (lane << 2);
    const bool isL = (lane == 0), isR = (lane == 31);
    const bool edgeL = (colBase == 0), edgeR = (colBase == W-4);
    const float* __restrict__ in     = (bufsel ? g_imgB : g_imgA) + (size_t)img*HW;
    float*       __restrict__ outImg = (bufsel ? g_imgA : g_imgB) + (size_t)img*HW;
    float*       __restrict__ skel   = g_skel + (size_t)img*HW;

    if (band == 0 || band == NBANDS-1)
        step2_body<true >(in, outImg, skel, R0row, colBase, isL, isR, edgeL, edgeR);
    else
        step2_body<false>(in, outImg, skel, R0row, colBase, isL, isR, edgeL, edgeR);
}

// ---------------------------------------------------------------------------
// endpoints: skel = 1 - q on load; ns = sum3x3(skel) + 9*center (zero pad);
// ep = exp(-(ns-11)^2)*center; partial sums per (img, band).
// ---------------------------------------------------------------------------
__global__ __launch_bounds__(128) void endpoint_kernel() {
    const int img = blockIdx.y;
    const int R0row = blockIdx.x * BH;
    const int lane = threadIdx.x & 31;
    const int colBase = ((threadIdx.x >> 5) << 7) + (lane << 2);
    const bool isL = (lane == 0), isR = (lane == 31);
    const bool edgeL = (colBase == 0), edgeR = (colBase == W-4);
    const float* __restrict__ sk = g_skel + (size_t)img*HW;

    const float4 Z = make_float4(0.f,0.f,0.f,0.f);
    float4 i0=Z, i1=Z; float L0w=0.f,L1w=0.f,R0x=0.f,R1x=0.f;
    float s0=0.f, sy=0.f, sx=0.f;

    const int rStart = R0row-1, rEnd = R0row+BH;    // BH+2 = 18 rows
    float4 nCur=Z; float nLw=0.f, nRx=0.f;
    if (rStart >= 0 && rStart < H) {
        const float* p = sk + rStart*W + colBase;
        float4 q = *(const float4*)p;
        nCur = make_float4(1.f-q.x, 1.f-q.y, 1.f-q.z, 1.f-q.w);
        if (isL && !edgeL) nLw = 1.f - p[-1];
        if (isR && !edgeR) nRx = 1.f - p[4];
    }

    #pragma unroll 2
    for (int t = 0; t < BH+2; t++) {
        const int r = rStart + t;
        float4 cur = nCur; float Lcw = nLw, Rcx = nRx;
        nCur = Z; nLw = 0.f; nRx = 0.f;
        {
            int rn = r + 1;
            if (rn <= rEnd && (unsigned)rn < (unsigned)H) {
                const float* p = sk + rn*W + colBase;
                float4 q = *(const float4*)p;
                nCur = make_float4(1.f-q.x, 1.f-q.y, 1.f-q.z, 1.f-q.w);
                if (isL && !edgeL) nLw = 1.f - p[-1];
                if (isR && !edgeR) nRx = 1.f - p[4];
            }
        }
        int k = r-1;
        if (k >= R0row && k < R0row+BH) {
            float4 vs;
            vs.x = i0.x + i1.x + cur.x;
            vs.y = i0.y + i1.y + cur.y;
            vs.z = i0.z + i1.z + cur.z;
            vs.w = i0.w + i1.w + cur.w;
            float vsL = L0w + L1w + Lcw;
            float vsR = R0x + R1x + Rcx;
            float sm1 = __shfl_up_sync(0xffffffffu, vs.w, 1); if (isL) sm1 = vsL;
            float sp1 = __shfl_down_sync(0xffffffffu, vs.x, 1); if (isR) sp1 = vsR;
            float ns0 = sm1 + vs.x + vs.y + 9.f*i1.x;
            float ns1 = vs.x + vs.y + vs.z + 9.f*i1.y;
            float ns2 = vs.y + vs.z + vs.w + 9.f*i1.z;
            float ns3 = vs.z + vs.w + sp1 + 9.f*i1.w;
            float d0 = ns0 - 11.f, d1 = ns1 - 11.f, d2 = ns2 - 11.f, d3 = ns3 - 11.f;
            float e0 = __expf(-d0*d0) * i1.x;
            float e1 = __expf(-d1*d1) * i1.y;
            float e2 = __expf(-d2*d2) * i1.z;
            float e3 = __expf(-d3*d3) * i1.w;
            float es = e0 + e1 + e2 + e3;
            s0 += es;
            sy += es * (float)k;
            sx += e0*(float)colBase + e1*(float)(colBase+1)
                + e2*(float)(colBase+2) + e3*(float)(colBase+3);
        }
        i0=i1; i1=cur; L0w=L1w; L1w=Lcw; R0x=R1x; R1x=Rcx;
    }

    __shared__ float s[3][128];
    s[0][threadIdx.x] = s0; s[1][threadIdx.x] = sy; s[2][threadIdx.x] = sx;
    __syncthreads();
    for (int off = 64; off > 0; off >>= 1) {
        if (threadIdx.x < off) {
            s[0][threadIdx.x] += s[0][threadIdx.x + off];
            s[1][threadIdx.x] += s[1][threadIdx.x + off];
            s[2][threadIdx.x] += s[2][threadIdx.x + off];
        }
        __syncthreads();
    }
    if (threadIdx.x == 0) {
        int o = (img*NBANDS + blockIdx.x)*3;
        g_epPart[o + 0] = s[0][0];
        g_epPart[o + 1] = s[1][0];
        g_epPart[o + 2] = s[2][0];
    }
}

// ---------------------------------------------------------------------------
// final: combine everything into the scalar loss.
// ---------------------------------------------------------------------------
__global__ __launch_bounds__(256) void final_kernel(float* __restrict__ out) {
    __shared__ float s[3][256];
    s[0][threadIdx.x] = g_dicePart[threadIdx.x*3 + 0];
    s[1][threadIdx.x] = g_dicePart[threadIdx.x*3 + 1];
    s[2][threadIdx.x] = g_dicePart[threadIdx.x*3 + 2];
    __syncthreads();
    for (int off = 128; off > 0; off >>= 1) {
        if (threadIdx.x < off) {
            s[0][threadIdx.x] += s[0][threadIdx.x + off];
            s[1][threadIdx.x] += s[1][threadIdx.x + off];
            s[2][threadIdx.x] += s[2][threadIdx.x + off];
        }
        __syncthreads();
    }
    __shared__ float S[NIMG], SY[NIMG], SX[NIMG];
    if (threadIdx.x < NIMG) {
        float t0 = 0.f, t1 = 0.f, t2 = 0.f;
        for (int bd = 0; bd < NBANDS; bd++) {
            int o = (threadIdx.x*NBANDS + bd)*3;
            t0 += g_epPart[o + 0];
            t1 += g_epPart[o + 1];
            t2 += g_epPart[o + 2];
        }
        S[threadIdx.x] = t0; SY[threadIdx.x] = t1; SX[threadIdx.x] = t2;
    }
    __syncthreads();
    if (threadIdx.x == 0) {
        float inter = s[0][0], sumT = s[1][0], sumP = s[2][0];
        float dice = 1.f - (2.f*inter + 1.f) / (sumT + sumP + 1.f);
        float distsum = 0.f, cntsum = 0.f;
        for (int b = 0; b < NB; b++) {
            float np = S[b], nt = S[NB + b];
            float tp = np + 1e-8f, tt = nt + 1e-8f;
            float ycp = SY[b] / tp,      xcp = SX[b] / tp;
            float yct = SY[NB+b] / tt,   xct = SX[NB+b] / tt;
            float dy = ycp - yct, dx = xcp - xct;
            distsum += sqrtf(dy*dy + dx*dx);
            cntsum  += fabsf(np - nt) / (np + nt + 1e-8f);
        }
        float diag = sqrtf((float)(H*H) + (float)(W*W));
        float distance_loss = (distsum / (float)NB) / (diag * 1.0f + 1e-8f);
        float count_penalty = cntsum / (float)NB;
        out[0] = 0.85f * dice + 0.15f * (distance_loss + count_penalty);
    }
}

// ---------------------------------------------------------------------------
extern "C" void kernel_launch(void* const* d_in, const int* in_sizes, int n_in,
                              void* d_out, int out_size) {
    const float* net = (const float*)d_in[0];
    const int*   yt  = (const int*)d_in[1];
    float* out = (float*)d_out;
    (void)in_sizes; (void)n_in; (void)out_size;

    prep_kernel<<<256, 256>>>(net, yt);

    dim3 grid(NBANDS, NIMG);
    sweep_init_kernel<<<grid, 128>>>();               // q init; img stays in A
    for (int k = 0; k < NFUSED; k++)
        sweep_step2_kernel<<<grid, 128>>>(k & 1);     // 2 iterations per launch
    endpoint_kernel<<<grid, 128>>>();
    final_kernel<<<1, 256>>>(out);
}